// round 15
// baseline (speedup 1.0000x reference)
#include <cuda_runtime.h>
#include <cuda_fp16.h>
#include <math.h>
#include <stdint.h>

#define D_MODEL 256
#define D_FFN   1024
#define NHEADS  8
#define NLEV    4
#define NPTS    4
#define HDIM    32
#define BATCH   2
#define SLEN    21760
#define NTOK    (BATCH * SLEN)   // 43520

// ================= scratch (device globals; no allocation allowed) =================
__device__ __align__(16) __half g_srcH[NTOK * D_MODEL];
__device__ __align__(16) __half g_qH[NTOK * D_MODEL];
__device__ __align__(16) __half g_sampH[NTOK * D_MODEL];
__device__ __align__(16) __half g_h2H[NTOK * D_MODEL];
__device__ __align__(16) __half g_ffnH[NTOK * D_FFN];
__device__ __align__(16) __half g_valueH[NTOK * D_MODEL];     // planar: [h][tok][dim]

__device__ float g_off[NTOK * D_MODEL];
__device__ float g_attn[NTOK * NHEADS * 16];                  // raw logits
__device__ float g_src2[NTOK * D_MODEL];

// weights transposed [N][K], fp16
__device__ __align__(16) __half w_v[256 * 256];
__device__ __align__(16) __half w_qa[384 * 256];              // 0-255: W_off, 256-383: W_attn
__device__ __align__(16) __half w_o[256 * 256];
__device__ __align__(16) __half w_f1[1024 * 256];
__device__ __align__(16) __half w_f2[256 * 1024];

// ================= helpers =================
__device__ __forceinline__ uint32_t smem_u32(const void* p) {
    uint32_t a;
    asm("{ .reg .u64 t; cvta.to.shared.u64 t, %1; cvt.u32.u64 %0, t; }" : "=r"(a) : "l"(p));
    return a;
}
__device__ __forceinline__ void ldm_x4(uint32_t* r, uint32_t addr) {
    asm volatile("ldmatrix.sync.aligned.m8n8.x4.shared.b16 {%0,%1,%2,%3}, [%4];"
                 : "=r"(r[0]), "=r"(r[1]), "=r"(r[2]), "=r"(r[3]) : "r"(addr));
}
__device__ __forceinline__ void mma16816(float* d, const uint32_t* a, const uint32_t* b) {
    asm volatile("mma.sync.aligned.m16n8k16.row.col.f32.f16.f16.f32 "
                 "{%0,%1,%2,%3}, {%4,%5,%6,%7}, {%8,%9}, {%0,%1,%2,%3};"
                 : "+f"(d[0]), "+f"(d[1]), "+f"(d[2]), "+f"(d[3])
                 : "r"(a[0]), "r"(a[1]), "r"(a[2]), "r"(a[3]), "r"(b[0]), "r"(b[1]));
}
__device__ __forceinline__ void cpa16(uint32_t dst, const void* src) {
    asm volatile("cp.async.cg.shared.global [%0], [%1], 16;" :: "r"(dst), "l"(src));
}

// ================= fp16 HMMA GEMM (R6 config): CTA 128x128, 4 warps of 64x64 =================
// 128 threads, BK=64, 3-stage cp.async ring, 2 CTAs/SM.
// EPI: 1 = gelu(x+bias) -> fp16; 2 = x+bias+aux(residual) -> fp32;
//      3 = dual (N=384): col<256 -> C(bias), col>=256 -> Cb(aux bias);
//      4 = fp16 planar value: Ch[((col>>5)*NTOK+row)*32 + (col&31)]  (Ch pre-offset for batch)
static const int LDSB = 144;                  // 64 fp16 (128 B) + 16 B pad
static const int BUFB = 128 * LDSB;           // 18432 B
static const int GEMM_SMEM = 6 * BUFB;        // 110592 B

template <int EPI>
__global__ void __launch_bounds__(128, 2) mma_gemm(
    const __half* __restrict__ A, const __half* __restrict__ B,
    const float* __restrict__ bias, const float* __restrict__ aux,
    float* __restrict__ C, float* __restrict__ Cb, __half* __restrict__ Ch,
    int N, int K)
{
    extern __shared__ __align__(16) char sm[];
    const uint32_t smb = smem_u32(sm);
    const int tid = threadIdx.x;
    const int wid = tid >> 5, lane = tid & 31;
    const int wm = wid >> 1, wn = wid & 1;                // 2x2 warps of 64x64
    const int m0 = blockIdx.y * 128, n0 = blockIdx.x * 128;
    const int S = K >> 6;

    float acc[4][8][4];
    #pragma unroll
    for (int i = 0; i < 4; i++)
        #pragma unroll
        for (int j = 0; j < 8; j++)
            #pragma unroll
            for (int r = 0; r < 4; r++) acc[i][j][r] = 0.f;

    auto prefetch = [&](int s) {
        int k0 = s << 6;
        const uint32_t ab = smb + (uint32_t)(s % 3) * (2u * BUFB);
        const uint32_t bb = ab + BUFB;
        #pragma unroll
        for (int i = 0; i < 16; i++) {
            int c = tid + (i << 7);                       // 0..2047
            int cc = c & 1023;
            int row = cc >> 3;
            int kc  = (cc & 7) << 3;
            uint32_t dst; const __half* src;
            if (c < 1024) {
                dst = ab + (uint32_t)(row * LDSB + kc * 2);
                src = A + (size_t)(m0 + row) * K + k0 + kc;
            } else {
                dst = bb + (uint32_t)(row * LDSB + kc * 2);
                src = B + (size_t)(n0 + row) * K + k0 + kc;
            }
            cpa16(dst, src);
        }
        asm volatile("cp.async.commit_group;");
    };

    prefetch(0);
    if (S > 1) prefetch(1);

    for (int s = 0; s < S; s++) {
        if (s + 1 < S) asm volatile("cp.async.wait_group 1;");
        else           asm volatile("cp.async.wait_group 0;");
        __syncthreads();
        if (s + 2 < S) prefetch(s + 2);

        const uint32_t ab = smb + (uint32_t)(s % 3) * (2u * BUFB);
        const uint32_t bb = ab + BUFB;
        const uint32_t aoff = ab + (uint32_t)(((lane & 15) + wm * 64) * LDSB + ((lane >> 4) << 4));
        const uint32_t boff = bb + (uint32_t)((((lane & 7) + ((lane >> 4) << 3)) + wn * 64) * LDSB
                                              + (((lane >> 3) & 1) << 4));
        #pragma unroll
        for (int ks = 0; ks < 4; ks++) {
            const uint32_t kb = (uint32_t)(ks << 5);
            uint32_t afr[4][4], bfr[8][2];
            #pragma unroll
            for (int mi = 0; mi < 4; mi++)
                ldm_x4(afr[mi], aoff + (uint32_t)(mi * 16 * LDSB) + kb);
            #pragma unroll
            for (int nj = 0; nj < 4; nj++) {
                uint32_t r[4];
                ldm_x4(r, boff + (uint32_t)(nj * 16 * LDSB) + kb);
                bfr[nj * 2][0] = r[0]; bfr[nj * 2][1] = r[1];
                bfr[nj * 2 + 1][0] = r[2]; bfr[nj * 2 + 1][1] = r[3];
            }
            #pragma unroll
            for (int mi = 0; mi < 4; mi++)
                #pragma unroll
                for (int ni = 0; ni < 8; ni++)
                    mma16816(acc[mi][ni], afr[mi], bfr[ni]);
        }
    }
    __syncthreads();

    // ---- epilogue: stage 64x64 per warp in smem (stride 68 floats), store coalesced ----
    float* ws = (float*)sm + wid * (64 * 68);
    const int er = lane >> 2, ec = (lane & 3) * 2;
    #pragma unroll
    for (int mi = 0; mi < 4; mi++)
        #pragma unroll
        for (int ni = 0; ni < 8; ni++) {
            *(float2*)&ws[(mi * 16 + er) * 68 + ni * 8 + ec]     = make_float2(acc[mi][ni][0], acc[mi][ni][1]);
            *(float2*)&ws[(mi * 16 + er + 8) * 68 + ni * 8 + ec] = make_float2(acc[mi][ni][2], acc[mi][ni][3]);
        }
    __syncwarp();

    const int gc0 = n0 + wn * 64 + lane;
    const int gc1 = gc0 + 32;
    float b0, b1;
    if (EPI == 3) {
        b0 = (gc0 < 256) ? bias[gc0] : aux[gc0 - 256];
        b1 = (gc1 < 256) ? bias[gc1] : aux[gc1 - 256];
    } else { b0 = bias[gc0]; b1 = bias[gc1]; }

    for (int r = 0; r < 64; r++) {
        const int gr = m0 + wm * 64 + r;
        float v0 = ws[r * 68 + lane] + b0;
        float v1 = ws[r * 68 + 32 + lane] + b1;
        if (EPI == 1) {
            v0 = 0.5f * v0 * (1.0f + erff(v0 * 0.70710678118654752f));
            v1 = 0.5f * v1 * (1.0f + erff(v1 * 0.70710678118654752f));
            Ch[(size_t)gr * N + gc0] = __float2half(v0);
            Ch[(size_t)gr * N + gc1] = __float2half(v1);
        } else if (EPI == 2) {
            C[(size_t)gr * N + gc0] = v0 + aux[(size_t)gr * N + gc0];
            C[(size_t)gr * N + gc1] = v1 + aux[(size_t)gr * N + gc1];
        } else if (EPI == 3) {
            if (gc0 < 256) C[(size_t)gr * 256 + gc0] = v0;
            else           Cb[(size_t)gr * 128 + (gc0 - 256)] = v0;
            if (gc1 < 256) C[(size_t)gr * 256 + gc1] = v1;
            else           Cb[(size_t)gr * 128 + (gc1 - 256)] = v1;
        } else {  // EPI == 4: planar value (Ch pre-offset by batch)
            Ch[((size_t)(gc0 >> 5) * NTOK + gr) * 32 + (gc0 & 31)] = __float2half(v0);
            Ch[((size_t)(gc1 >> 5) * NTOK + gr) * 32 + (gc1 & 31)] = __float2half(v1);
        }
    }
}

// ================= pre: warp-per-token + weight prep slice =================
__global__ void pre_kernel(const float* __restrict__ x,
                           const float* __restrict__ gamma,
                           const float* __restrict__ beta,
                           const float* __restrict__ pos,
                           const float* __restrict__ Wv, const float* __restrict__ Wo,
                           const float* __restrict__ Wa, const float* __restrict__ Wout,
                           const float* __restrict__ Wf1, const float* __restrict__ Wf2) {
    const int wid = threadIdx.x >> 5, lane = threadIdx.x & 31;
    const int t = blockIdx.x * 8 + wid;

    int gid = blockIdx.x * 256 + threadIdx.x;
    if (gid < 753664) {
        int i = gid;
        const float* W; __half* B; int K, N, rowOff, i2;
        if (i < 65536)        { W = Wv;  B = w_v;  K = 256;  N = 256;  rowOff = 0;   i2 = i; }
        else if (i < 131072)  { W = Wo;  B = w_qa; K = 256;  N = 256;  rowOff = 0;   i2 = i - 65536; }
        else if (i < 163840)  { W = Wa;  B = w_qa; K = 256;  N = 128;  rowOff = 256; i2 = i - 131072; }
        else if (i < 229376)  { W = Wout;B = w_o;  K = 256;  N = 256;  rowOff = 0;   i2 = i - 163840; }
        else if (i < 491520)  { W = Wf1; B = w_f1; K = 256;  N = 1024; rowOff = 0;   i2 = i - 229376; }
        else                  { W = Wf2; B = w_f2; K = 1024; N = 256;  rowOff = 0;   i2 = i - 491520; }
        int k = i2 / N, n = i2 - k * N;
        B[(size_t)(n + rowOff) * K + k] = __float2half(W[i2]);
    }

    const float4* rowX = (const float4*)(x + (size_t)t * 256);
    float4 va = rowX[lane], vb = rowX[lane + 32];

    {
        uint2 o0, o1;
        __half2 p0 = __floats2half2_rn(va.x, va.y), p1 = __floats2half2_rn(va.z, va.w);
        __half2 p2 = __floats2half2_rn(vb.x, vb.y), p3 = __floats2half2_rn(vb.z, vb.w);
        o0.x = *(uint32_t*)&p0; o0.y = *(uint32_t*)&p1;
        o1.x = *(uint32_t*)&p2; o1.y = *(uint32_t*)&p3;
        ((uint2*)g_srcH)[(size_t)t * 64 + lane] = o0;
        ((uint2*)g_srcH)[(size_t)t * 64 + 32 + lane] = o1;
    }

    float s  = va.x + va.y + va.z + va.w + vb.x + vb.y + vb.z + vb.w;
    float s2 = va.x*va.x + va.y*va.y + va.z*va.z + va.w*va.w
             + vb.x*vb.x + vb.y*vb.y + vb.z*vb.z + vb.w*vb.w;
    #pragma unroll
    for (int o = 16; o; o >>= 1) {
        s  += __shfl_xor_sync(0xffffffffu, s,  o);
        s2 += __shfl_xor_sync(0xffffffffu, s2, o);
    }
    float mu  = s * (1.0f / D_MODEL);
    float var = s2 * (1.0f / D_MODEL) - mu * mu;
    float rr  = rsqrtf(var + 1e-5f);

    const float4* rowP = (const float4*)(pos + (size_t)t * 256);
    const float4* gmA = (const float4*)gamma;
    const float4* btA = (const float4*)beta;
    #pragma unroll
    for (int hfl = 0; hfl < 2; hfl++) {
        int idx = lane + hfl * 32;
        float4 v = hfl ? vb : va;
        float4 p = rowP[idx];
        float4 gm = gmA[idx], bt = btA[idx];
        float y0 = (v.x - mu) * rr * gm.x + bt.x + p.x;
        float y1 = (v.y - mu) * rr * gm.y + bt.y + p.y;
        float y2 = (v.z - mu) * rr * gm.z + bt.z + p.z;
        float y3 = (v.w - mu) * rr * gm.w + bt.w + p.w;
        uint2 o;
        __half2 q0 = __floats2half2_rn(y0, y1), q1 = __floats2half2_rn(y2, y3);
        o.x = *(uint32_t*)&q0; o.y = *(uint32_t*)&q1;
        ((uint2*)g_qH)[(size_t)t * 64 + idx] = o;
    }
}

// ================= ln2: warp-per-token, batch slice =================
__global__ void ln2_kernel(const float* __restrict__ x,
                           const float* __restrict__ gamma,
                           const float* __restrict__ beta,
                           int tokOff) {
    const int wid = threadIdx.x >> 5, lane = threadIdx.x & 31;
    const int t = tokOff + blockIdx.x * 8 + wid;

    const float4* rowX = (const float4*)(x + (size_t)t * 256);
    float4 va = rowX[lane], vb = rowX[lane + 32];

    float s  = va.x + va.y + va.z + va.w + vb.x + vb.y + vb.z + vb.w;
    float s2 = va.x*va.x + va.y*va.y + va.z*va.z + va.w*va.w
             + vb.x*vb.x + vb.y*vb.y + vb.z*vb.z + vb.w*vb.w;
    #pragma unroll
    for (int o = 16; o; o >>= 1) {
        s  += __shfl_xor_sync(0xffffffffu, s,  o);
        s2 += __shfl_xor_sync(0xffffffffu, s2, o);
    }
    float mu  = s * (1.0f / D_MODEL);
    float var = s2 * (1.0f / D_MODEL) - mu * mu;
    float rr  = rsqrtf(var + 1e-5f);

    const float4* gmA = (const float4*)gamma;
    const float4* btA = (const float4*)beta;
    #pragma unroll
    for (int hfl = 0; hfl < 2; hfl++) {
        int idx = lane + hfl * 32;
        float4 v = hfl ? vb : va;
        float4 gm = gmA[idx], bt = btA[idx];
        float y0 = (v.x - mu) * rr * gm.x + bt.x;
        float y1 = (v.y - mu) * rr * gm.y + bt.y;
        float y2 = (v.z - mu) * rr * gm.z + bt.z;
        float y3 = (v.w - mu) * rr * gm.w + bt.w;
        uint2 o;
        __half2 q0 = __floats2half2_rn(y0, y1), q1 = __floats2half2_rn(y2, y3);
        o.x = *(uint32_t*)&q0; o.y = *(uint32_t*)&q1;
        ((uint2*)g_h2H)[(size_t)t * 64 + idx] = o;
    }
}

// ================= deform: fp16 bilinear blend, batch slice =================
__global__ void deform_kernel(const float* __restrict__ ref, int bIdx) {
    const int lvH[4] = {128, 64, 32, 16};
    const int lvW[4] = {128, 64, 32, 16};
    const int lvS[4] = {0, 16384, 20480, 21504};

    int g = blockIdx.x * 8 + (threadIdx.x >> 5);    // 0 .. SLEN*NHEADS-1
    int lane = threadIdx.x & 31;
    int qi = g / NHEADS;
    int h  = g - qi * NHEADS;
    int tok = bIdx * SLEN + qi;

    float offv = g_off[(size_t)tok * 256 + h * 32 + lane];
    float refv = (lane < 8) ? ref[(size_t)tok * 8 + lane] : 0.f;
    float lg   = (lane < 16) ? g_attn[(size_t)tok * 128 + h * 16 + lane] : -1e30f;

    float mx = lg;
    #pragma unroll
    for (int o = 8; o; o >>= 1) mx = fmaxf(mx, __shfl_xor_sync(0xffffffffu, mx, o));
    float e = (lane < 16) ? __expf(lg - mx) : 0.f;
    float se = e;
    #pragma unroll
    for (int o = 8; o; o >>= 1) se += __shfl_xor_sync(0xffffffffu, se, o);
    float wnorm = e / se;

    uint32_t c00, c01, c10, c11;
    uint32_t uh00, uh01, uh10, uh11;
    float wat;
    {
        const int sidx = lane & 15;
        const int lvl  = sidx >> 2;
        const int Ww = lvW[lvl], Hh = lvH[lvl];
        float rx = __shfl_sync(0xffffffffu, refv, lvl * 2 + 0);
        float ry = __shfl_sync(0xffffffffu, refv, lvl * 2 + 1);
        float ox = __shfl_sync(0xffffffffu, offv, sidx * 2 + 0);
        float oy = __shfl_sync(0xffffffffu, offv, sidx * 2 + 1);
        wat = __shfl_sync(0xffffffffu, wnorm, sidx);

        float x = fmaf(rx, (float)Ww, ox) - 0.5f;
        float y = fmaf(ry, (float)Hh, oy) - 0.5f;
        float x0f = floorf(x), y0f = floorf(y);
        int x0 = (int)x0f, y0 = (int)y0f;
        float wx = x - x0f, wy = y - y0f;
        int x1 = x0 + 1, y1 = y0 + 1;

        float vx0 = ((unsigned)x0 < (unsigned)Ww) ? 1.f : 0.f;
        float vx1 = ((unsigned)x1 < (unsigned)Ww) ? 1.f : 0.f;
        float vy0 = ((unsigned)y0 < (unsigned)Hh) ? 1.f : 0.f;
        float vy1 = ((unsigned)y1 < (unsigned)Hh) ? 1.f : 0.f;

        int x0c = min(max(x0, 0), Ww - 1), x1c = min(max(x1, 0), Ww - 1);
        int y0c = min(max(y0, 0), Hh - 1), y1c = min(max(y1, 0), Hh - 1);

        uint32_t pb = (uint32_t)h * NTOK + (uint32_t)(bIdx * SLEN + lvS[lvl]);
        uint32_t r0 = pb + (uint32_t)(y0c * Ww), r1 = pb + (uint32_t)(y1c * Ww);
        c00 = (r0 + (uint32_t)x0c) * 8u; c01 = (r0 + (uint32_t)x1c) * 8u;
        c10 = (r1 + (uint32_t)x0c) * 8u; c11 = (r1 + (uint32_t)x1c) * 8u;

        float wx0 = 1.f - wx, wy0 = 1.f - wy;
        __half2 t0 = __float2half2_rn(wx0 * wy0 * (vx0 * vy0));
        __half2 t1 = __float2half2_rn(wx  * wy0 * (vx1 * vy0));
        __half2 t2 = __float2half2_rn(wx0 * wy  * (vx0 * vy1));
        __half2 t3 = __float2half2_rn(wx  * wy  * (vx1 * vy1));
        uh00 = *(uint32_t*)&t0; uh01 = *(uint32_t*)&t1;
        uh10 = *(uint32_t*)&t2; uh11 = *(uint32_t*)&t3;
    }

    const int q = lane >> 3;
    const uint32_t li = (uint32_t)(lane & 7);
    const uint2* vbase = (const uint2*)g_valueH;
    float4 acc = make_float4(0.f, 0.f, 0.f, 0.f);
    #pragma unroll
    for (int it = 0; it < 4; it++) {
        const int sp = it * 4 + q;
        uint32_t a00 = __shfl_sync(0xffffffffu, c00, sp) + li;
        uint32_t a01 = __shfl_sync(0xffffffffu, c01, sp) + li;
        uint32_t a10 = __shfl_sync(0xffffffffu, c10, sp) + li;
        uint32_t a11 = __shfl_sync(0xffffffffu, c11, sp) + li;
        uint32_t b00 = __shfl_sync(0xffffffffu, uh00, sp);
        uint32_t b01 = __shfl_sync(0xffffffffu, uh01, sp);
        uint32_t b10 = __shfl_sync(0xffffffffu, uh10, sp);
        uint32_t b11 = __shfl_sync(0xffffffffu, uh11, sp);
        float w = __shfl_sync(0xffffffffu, wat, sp);
        uint2 r00 = vbase[a00];
        uint2 r01 = vbase[a01];
        uint2 r10 = vbase[a10];
        uint2 r11 = vbase[a11];
        __half2 blo = __hmul2(*(__half2*)&b00, *(__half2*)&r00.x);
        blo = __hfma2(*(__half2*)&b01, *(__half2*)&r01.x, blo);
        blo = __hfma2(*(__half2*)&b10, *(__half2*)&r10.x, blo);
        blo = __hfma2(*(__half2*)&b11, *(__half2*)&r11.x, blo);
        __half2 bhi = __hmul2(*(__half2*)&b00, *(__half2*)&r00.y);
        bhi = __hfma2(*(__half2*)&b01, *(__half2*)&r01.y, bhi);
        bhi = __hfma2(*(__half2*)&b10, *(__half2*)&r10.y, bhi);
        bhi = __hfma2(*(__half2*)&b11, *(__half2*)&r11.y, bhi);
        float2 f0 = __half22float2(blo);
        float2 f1 = __half22float2(bhi);
        acc.x = fmaf(f0.x, w, acc.x);
        acc.y = fmaf(f0.y, w, acc.y);
        acc.z = fmaf(f1.x, w, acc.z);
        acc.w = fmaf(f1.y, w, acc.w);
    }
    #pragma unroll
    for (int o = 8; o <= 16; o <<= 1) {
        acc.x += __shfl_xor_sync(0xffffffffu, acc.x, o);
        acc.y += __shfl_xor_sync(0xffffffffu, acc.y, o);
        acc.z += __shfl_xor_sync(0xffffffffu, acc.z, o);
        acc.w += __shfl_xor_sync(0xffffffffu, acc.w, o);
    }
    if (lane < 8) {
        uint2 outv;
        __half2 h0 = __floats2half2_rn(acc.x, acc.y);
        __half2 h1 = __floats2half2_rn(acc.z, acc.w);
        outv.x = *(const uint32_t*)&h0;
        outv.y = *(const uint32_t*)&h1;
        ((uint2*)g_sampH)[(uint32_t)tok * 64u + (uint32_t)h * 8u + li] = outv;
    }
}

// ================= launch: batch-split, phase-staggered dual-stream pipeline =================
extern "C" void kernel_launch(void* const* d_in, const int* in_sizes, int n_in,
                              void* d_out, int out_size) {
    const float* src  = (const float*)d_in[0];
    const float* pos  = (const float*)d_in[1];
    const float* refp = (const float*)d_in[2];
    const float* n1g = (const float*)d_in[5];
    const float* n1b = (const float*)d_in[6];
    const float* n2g = (const float*)d_in[7];
    const float* n2b = (const float*)d_in[8];
    const float* Wv  = (const float*)d_in[9];
    const float* bv  = (const float*)d_in[10];
    const float* Wo  = (const float*)d_in[11];
    const float* bo  = (const float*)d_in[12];
    const float* Wa  = (const float*)d_in[13];
    const float* ba  = (const float*)d_in[14];
    const float* Wout= (const float*)d_in[15];
    const float* bout= (const float*)d_in[16];
    const float* Wf1 = (const float*)d_in[17];
    const float* bf1 = (const float*)d_in[18];
    const float* Wf2 = (const float*)d_in[19];
    const float* bf2 = (const float*)d_in[20];
    float* out = (float*)d_out;

    __half *srcH, *qH, *sampH, *h2H, *ffnH, *valH;
    __half *wv, *wqa, *wo, *wf1, *wf2;
    float *pOff, *pAttn, *pSrc2;
    cudaGetSymbolAddress((void**)&srcH, g_srcH);
    cudaGetSymbolAddress((void**)&qH,   g_qH);
    cudaGetSymbolAddress((void**)&sampH,g_sampH);
    cudaGetSymbolAddress((void**)&h2H,  g_h2H);
    cudaGetSymbolAddress((void**)&ffnH, g_ffnH);
    cudaGetSymbolAddress((void**)&valH, g_valueH);
    cudaGetSymbolAddress((void**)&wv,   w_v);
    cudaGetSymbolAddress((void**)&wqa,  w_qa);
    cudaGetSymbolAddress((void**)&wo,   w_o);
    cudaGetSymbolAddress((void**)&wf1,  w_f1);
    cudaGetSymbolAddress((void**)&wf2,  w_f2);
    cudaGetSymbolAddress((void**)&pOff,  g_off);
    cudaGetSymbolAddress((void**)&pAttn, g_attn);
    cudaGetSymbolAddress((void**)&pSrc2, g_src2);

    cudaFuncSetAttribute(mma_gemm<1>, cudaFuncAttributeMaxDynamicSharedMemorySize, GEMM_SMEM);
    cudaFuncSetAttribute(mma_gemm<2>, cudaFuncAttributeMaxDynamicSharedMemorySize, GEMM_SMEM);
    cudaFuncSetAttribute(mma_gemm<3>, cudaFuncAttributeMaxDynamicSharedMemorySize, GEMM_SMEM);
    cudaFuncSetAttribute(mma_gemm<4>, cudaFuncAttributeMaxDynamicSharedMemorySize, GEMM_SMEM);

    static cudaStream_t sB = nullptr;
    static cudaEvent_t evQA0 = nullptr, evB = nullptr;
    if (!sB) {
        cudaStreamCreateWithFlags(&sB, cudaStreamNonBlocking);
        cudaEventCreateWithFlags(&evQA0, cudaEventDisableTiming);
        cudaEventCreateWithFlags(&evB,   cudaEventDisableTiming);
    }

    dim3 t256(256), t128(128);
    const int MBb = SLEN / 128;   // 170 row-tiles per batch

    // stage 0: shared prep (weights + src/q fp16) on main stream
    pre_kernel<<<NTOK / 8, t256>>>(src, n1g, n1b, pos, Wv, Wo, Wa, Wout, Wf1, Wf2);

    // ---- batch 0 front GEMMs on main stream ----
    {
        const size_t to = 0;
        mma_gemm<4><<<dim3(2, MBb), t128, GEMM_SMEM>>>(srcH, wv, bv, nullptr,
                                                       nullptr, nullptr, valH, 256, 256);
        mma_gemm<3><<<dim3(3, MBb), t128, GEMM_SMEM>>>(qH, wqa, bo, ba,
                                                       pOff, pAttn, nullptr, 384, 256);
    }
    // stagger: stream B starts its GEMMs only after batch-0 GEMMs complete,
    // so b1 GEMMs (tensor) overlap b0 deform (ALU), and b0 FFN overlaps b1 deform.
    cudaEventRecord(evQA0, 0);
    cudaStreamWaitEvent(sB, evQA0, 0);

    // ---- batch 0 back half on main stream ----
    {
        const size_t to = 0;
        deform_kernel<<<(SLEN * NHEADS) / 8, t256>>>(refp, 0);
        mma_gemm<2><<<dim3(2, MBb), t128, GEMM_SMEM>>>(sampH, wo, bout, src,
                                                       pSrc2, nullptr, nullptr, 256, 256);
        ln2_kernel<<<SLEN / 8, t256>>>(pSrc2, n2g, n2b, 0);
        mma_gemm<1><<<dim3(8, MBb), t128, GEMM_SMEM>>>(h2H, wf1, bf1, nullptr,
                                                       nullptr, nullptr, ffnH, 1024, 256);
        mma_gemm<2><<<dim3(2, MBb), t128, GEMM_SMEM>>>(ffnH, wf2, bf2, pSrc2,
                                                       out, nullptr, nullptr, 256, 1024);
    }

    // ---- batch 1 full chain on stream B ----
    {
        const size_t to = (size_t)SLEN;
        const __half* srcHb = srcH + to * 256;
        const __half* qHb   = qH   + to * 256;
        __half*  valHb  = valH + to * 32;
        float*   offb   = pOff  + to * 256;
        float*   attnb  = pAttn + to * 128;
        __half*  sampb  = sampH + to * 256;
        float*   src2b  = pSrc2 + to * 256;
        const float* srcb = src + to * 256;
        __half*  h2b    = h2H  + to * 256;
        __half*  ffnb   = ffnH + to * 1024;
        float*   outb   = out  + to * 256;

        mma_gemm<4><<<dim3(2, MBb), t128, GEMM_SMEM, sB>>>(srcHb, wv, bv, nullptr,
                                                           nullptr, nullptr, valHb, 256, 256);
        mma_gemm<3><<<dim3(3, MBb), t128, GEMM_SMEM, sB>>>(qHb, wqa, bo, ba,
                                                           offb, attnb, nullptr, 384, 256);
        deform_kernel<<<(SLEN * NHEADS) / 8, t256, 0, sB>>>(refp, 1);
        mma_gemm<2><<<dim3(2, MBb), t128, GEMM_SMEM, sB>>>(sampb, wo, bout, srcb,
                                                           src2b, nullptr, nullptr, 256, 256);
        ln2_kernel<<<SLEN / 8, t256, 0, sB>>>(pSrc2, n2g, n2b, (int)to);
        mma_gemm<1><<<dim3(8, MBb), t128, GEMM_SMEM, sB>>>(h2b, wf1, bf1, nullptr,
                                                           nullptr, nullptr, ffnb, 1024, 256);
        mma_gemm<2><<<dim3(2, MBb), t128, GEMM_SMEM, sB>>>(ffnb, wf2, bf2, src2b,
                                                           outb, nullptr, nullptr, 256, 1024);
    }

    // join sB back into the main stream
    cudaEventRecord(evB, sB);
    cudaStreamWaitEvent(0, evB, 0);
}

// round 16
// speedup vs baseline: 1.1210x; 1.1210x over previous
#include <cuda_runtime.h>
#include <cuda_fp16.h>
#include <math.h>
#include <stdint.h>

#define D_MODEL 256
#define D_FFN   1024
#define NHEADS  8
#define NLEV    4
#define NPTS    4
#define HDIM    32
#define BATCH   2
#define SLEN    21760
#define NTOK    (BATCH * SLEN)   // 43520

// ================= scratch (device globals; no allocation allowed) =================
__device__ __align__(16) __half g_srcH[NTOK * D_MODEL];
__device__ __align__(16) __half g_qH[NTOK * D_MODEL];
__device__ __align__(16) __half g_sampH[NTOK * D_MODEL];
__device__ __align__(16) __half g_h2H[NTOK * D_MODEL];
__device__ __align__(16) __half g_ffnH[NTOK * D_FFN];
__device__ __align__(16) __half g_valueH[NTOK * D_MODEL];     // planar: [h][tok][dim]

__device__ float g_off[NTOK * D_MODEL];
__device__ float g_attn[NTOK * NHEADS * 16];                  // raw logits
__device__ float g_src2[NTOK * D_MODEL];

// weights transposed [N][K], fp16
__device__ __align__(16) __half w_v[256 * 256];
__device__ __align__(16) __half w_qa[384 * 256];              // 0-255: W_off, 256-383: W_attn
__device__ __align__(16) __half w_o[256 * 256];
__device__ __align__(16) __half w_f1[1024 * 256];
__device__ __align__(16) __half w_f2[256 * 1024];

// ================= helpers =================
__device__ __forceinline__ uint32_t smem_u32(const void* p) {
    uint32_t a;
    asm("{ .reg .u64 t; cvta.to.shared.u64 t, %1; cvt.u32.u64 %0, t; }" : "=r"(a) : "l"(p));
    return a;
}
__device__ __forceinline__ void ldm_x4(uint32_t* r, uint32_t addr) {
    asm volatile("ldmatrix.sync.aligned.m8n8.x4.shared.b16 {%0,%1,%2,%3}, [%4];"
                 : "=r"(r[0]), "=r"(r[1]), "=r"(r[2]), "=r"(r[3]) : "r"(addr));
}
__device__ __forceinline__ void mma16816(float* d, const uint32_t* a, const uint32_t* b) {
    asm volatile("mma.sync.aligned.m16n8k16.row.col.f32.f16.f16.f32 "
                 "{%0,%1,%2,%3}, {%4,%5,%6,%7}, {%8,%9}, {%0,%1,%2,%3};"
                 : "+f"(d[0]), "+f"(d[1]), "+f"(d[2]), "+f"(d[3])
                 : "r"(a[0]), "r"(a[1]), "r"(a[2]), "r"(a[3]), "r"(b[0]), "r"(b[1]));
}
__device__ __forceinline__ void cpa16(uint32_t dst, const void* src) {
    asm volatile("cp.async.cg.shared.global [%0], [%1], 16;" :: "r"(dst), "l"(src));
}

// ================= fp16 HMMA GEMM (R6 config): CTA 128x128, 4 warps of 64x64 =================
// 128 threads, BK=64, 3-stage cp.async ring, 2 CTAs/SM.
// EPI: 1 = gelu(x+bias) -> fp16; 2 = x+bias+aux(residual) -> fp32;
//      3 = dual (N=384): col<256 -> C(bias), col>=256 -> Cb(aux bias);
//      4 = fp16 planar value: Ch[((col>>5)*NTOK+row)*32 + (col&31)]  (Ch pre-offset for batch)
static const int LDSB = 144;                  // 64 fp16 (128 B) + 16 B pad
static const int BUFB = 128 * LDSB;           // 18432 B
static const int GEMM_SMEM = 6 * BUFB;        // 110592 B

template <int EPI>
__global__ void __launch_bounds__(128, 2) mma_gemm(
    const __half* __restrict__ A, const __half* __restrict__ B,
    const float* __restrict__ bias, const float* __restrict__ aux,
    float* __restrict__ C, float* __restrict__ Cb, __half* __restrict__ Ch,
    int N, int K)
{
    extern __shared__ __align__(16) char sm[];
    const uint32_t smb = smem_u32(sm);
    const int tid = threadIdx.x;
    const int wid = tid >> 5, lane = tid & 31;
    const int wm = wid >> 1, wn = wid & 1;                // 2x2 warps of 64x64
    const int m0 = blockIdx.y * 128, n0 = blockIdx.x * 128;
    const int S = K >> 6;

    float acc[4][8][4];
    #pragma unroll
    for (int i = 0; i < 4; i++)
        #pragma unroll
        for (int j = 0; j < 8; j++)
            #pragma unroll
            for (int r = 0; r < 4; r++) acc[i][j][r] = 0.f;

    auto prefetch = [&](int s) {
        int k0 = s << 6;
        const uint32_t ab = smb + (uint32_t)(s % 3) * (2u * BUFB);
        const uint32_t bb = ab + BUFB;
        #pragma unroll
        for (int i = 0; i < 16; i++) {
            int c = tid + (i << 7);                       // 0..2047
            int cc = c & 1023;
            int row = cc >> 3;
            int kc  = (cc & 7) << 3;
            uint32_t dst; const __half* src;
            if (c < 1024) {
                dst = ab + (uint32_t)(row * LDSB + kc * 2);
                src = A + (size_t)(m0 + row) * K + k0 + kc;
            } else {
                dst = bb + (uint32_t)(row * LDSB + kc * 2);
                src = B + (size_t)(n0 + row) * K + k0 + kc;
            }
            cpa16(dst, src);
        }
        asm volatile("cp.async.commit_group;");
    };

    prefetch(0);
    if (S > 1) prefetch(1);

    for (int s = 0; s < S; s++) {
        if (s + 1 < S) asm volatile("cp.async.wait_group 1;");
        else           asm volatile("cp.async.wait_group 0;");
        __syncthreads();
        if (s + 2 < S) prefetch(s + 2);

        const uint32_t ab = smb + (uint32_t)(s % 3) * (2u * BUFB);
        const uint32_t bb = ab + BUFB;
        const uint32_t aoff = ab + (uint32_t)(((lane & 15) + wm * 64) * LDSB + ((lane >> 4) << 4));
        const uint32_t boff = bb + (uint32_t)((((lane & 7) + ((lane >> 4) << 3)) + wn * 64) * LDSB
                                              + (((lane >> 3) & 1) << 4));
        #pragma unroll
        for (int ks = 0; ks < 4; ks++) {
            const uint32_t kb = (uint32_t)(ks << 5);
            uint32_t afr[4][4], bfr[8][2];
            #pragma unroll
            for (int mi = 0; mi < 4; mi++)
                ldm_x4(afr[mi], aoff + (uint32_t)(mi * 16 * LDSB) + kb);
            #pragma unroll
            for (int nj = 0; nj < 4; nj++) {
                uint32_t r[4];
                ldm_x4(r, boff + (uint32_t)(nj * 16 * LDSB) + kb);
                bfr[nj * 2][0] = r[0]; bfr[nj * 2][1] = r[1];
                bfr[nj * 2 + 1][0] = r[2]; bfr[nj * 2 + 1][1] = r[3];
            }
            #pragma unroll
            for (int mi = 0; mi < 4; mi++)
                #pragma unroll
                for (int ni = 0; ni < 8; ni++)
                    mma16816(acc[mi][ni], afr[mi], bfr[ni]);
        }
    }
    __syncthreads();

    // ---- epilogue: stage 64x64 per warp in smem (stride 68 floats), store coalesced ----
    float* ws = (float*)sm + wid * (64 * 68);
    const int er = lane >> 2, ec = (lane & 3) * 2;
    #pragma unroll
    for (int mi = 0; mi < 4; mi++)
        #pragma unroll
        for (int ni = 0; ni < 8; ni++) {
            *(float2*)&ws[(mi * 16 + er) * 68 + ni * 8 + ec]     = make_float2(acc[mi][ni][0], acc[mi][ni][1]);
            *(float2*)&ws[(mi * 16 + er + 8) * 68 + ni * 8 + ec] = make_float2(acc[mi][ni][2], acc[mi][ni][3]);
        }
    __syncwarp();

    const int gc0 = n0 + wn * 64 + lane;
    const int gc1 = gc0 + 32;
    float b0, b1;
    if (EPI == 3) {
        b0 = (gc0 < 256) ? bias[gc0] : aux[gc0 - 256];
        b1 = (gc1 < 256) ? bias[gc1] : aux[gc1 - 256];
    } else { b0 = bias[gc0]; b1 = bias[gc1]; }

    for (int r = 0; r < 64; r++) {
        const int gr = m0 + wm * 64 + r;
        float v0 = ws[r * 68 + lane] + b0;
        float v1 = ws[r * 68 + 32 + lane] + b1;
        if (EPI == 1) {
            v0 = 0.5f * v0 * (1.0f + erff(v0 * 0.70710678118654752f));
            v1 = 0.5f * v1 * (1.0f + erff(v1 * 0.70710678118654752f));
            Ch[(size_t)gr * N + gc0] = __float2half(v0);
            Ch[(size_t)gr * N + gc1] = __float2half(v1);
        } else if (EPI == 2) {
            C[(size_t)gr * N + gc0] = v0 + aux[(size_t)gr * N + gc0];
            C[(size_t)gr * N + gc1] = v1 + aux[(size_t)gr * N + gc1];
        } else if (EPI == 3) {
            if (gc0 < 256) C[(size_t)gr * 256 + gc0] = v0;
            else           Cb[(size_t)gr * 128 + (gc0 - 256)] = v0;
            if (gc1 < 256) C[(size_t)gr * 256 + gc1] = v1;
            else           Cb[(size_t)gr * 128 + (gc1 - 256)] = v1;
        } else {  // EPI == 4: planar value (Ch pre-offset by batch)
            Ch[((size_t)(gc0 >> 5) * NTOK + gr) * 32 + (gc0 & 31)] = __float2half(v0);
            Ch[((size_t)(gc1 >> 5) * NTOK + gr) * 32 + (gc1 & 31)] = __float2half(v1);
        }
    }
}

// ================= pre: warp-per-token + weight prep slice =================
__global__ void pre_kernel(const float* __restrict__ x,
                           const float* __restrict__ gamma,
                           const float* __restrict__ beta,
                           const float* __restrict__ pos,
                           const float* __restrict__ Wv, const float* __restrict__ Wo,
                           const float* __restrict__ Wa, const float* __restrict__ Wout,
                           const float* __restrict__ Wf1, const float* __restrict__ Wf2) {
    const int wid = threadIdx.x >> 5, lane = threadIdx.x & 31;
    const int t = blockIdx.x * 8 + wid;

    int gid = blockIdx.x * 256 + threadIdx.x;
    if (gid < 753664) {
        int i = gid;
        const float* W; __half* B; int K, N, rowOff, i2;
        if (i < 65536)        { W = Wv;  B = w_v;  K = 256;  N = 256;  rowOff = 0;   i2 = i; }
        else if (i < 131072)  { W = Wo;  B = w_qa; K = 256;  N = 256;  rowOff = 0;   i2 = i - 65536; }
        else if (i < 163840)  { W = Wa;  B = w_qa; K = 256;  N = 128;  rowOff = 256; i2 = i - 131072; }
        else if (i < 229376)  { W = Wout;B = w_o;  K = 256;  N = 256;  rowOff = 0;   i2 = i - 163840; }
        else if (i < 491520)  { W = Wf1; B = w_f1; K = 256;  N = 1024; rowOff = 0;   i2 = i - 229376; }
        else                  { W = Wf2; B = w_f2; K = 1024; N = 256;  rowOff = 0;   i2 = i - 491520; }
        int k = i2 / N, n = i2 - k * N;
        B[(size_t)(n + rowOff) * K + k] = __float2half(W[i2]);
    }

    const float4* rowX = (const float4*)(x + (size_t)t * 256);
    float4 va = rowX[lane], vb = rowX[lane + 32];

    {
        uint2 o0, o1;
        __half2 p0 = __floats2half2_rn(va.x, va.y), p1 = __floats2half2_rn(va.z, va.w);
        __half2 p2 = __floats2half2_rn(vb.x, vb.y), p3 = __floats2half2_rn(vb.z, vb.w);
        o0.x = *(uint32_t*)&p0; o0.y = *(uint32_t*)&p1;
        o1.x = *(uint32_t*)&p2; o1.y = *(uint32_t*)&p3;
        ((uint2*)g_srcH)[(size_t)t * 64 + lane] = o0;
        ((uint2*)g_srcH)[(size_t)t * 64 + 32 + lane] = o1;
    }

    float s  = va.x + va.y + va.z + va.w + vb.x + vb.y + vb.z + vb.w;
    float s2 = va.x*va.x + va.y*va.y + va.z*va.z + va.w*va.w
             + vb.x*vb.x + vb.y*vb.y + vb.z*vb.z + vb.w*vb.w;
    #pragma unroll
    for (int o = 16; o; o >>= 1) {
        s  += __shfl_xor_sync(0xffffffffu, s,  o);
        s2 += __shfl_xor_sync(0xffffffffu, s2, o);
    }
    float mu  = s * (1.0f / D_MODEL);
    float var = s2 * (1.0f / D_MODEL) - mu * mu;
    float rr  = rsqrtf(var + 1e-5f);

    const float4* rowP = (const float4*)(pos + (size_t)t * 256);
    const float4* gmA = (const float4*)gamma;
    const float4* btA = (const float4*)beta;
    #pragma unroll
    for (int hfl = 0; hfl < 2; hfl++) {
        int idx = lane + hfl * 32;
        float4 v = hfl ? vb : va;
        float4 p = rowP[idx];
        float4 gm = gmA[idx], bt = btA[idx];
        float y0 = (v.x - mu) * rr * gm.x + bt.x + p.x;
        float y1 = (v.y - mu) * rr * gm.y + bt.y + p.y;
        float y2 = (v.z - mu) * rr * gm.z + bt.z + p.z;
        float y3 = (v.w - mu) * rr * gm.w + bt.w + p.w;
        uint2 o;
        __half2 q0 = __floats2half2_rn(y0, y1), q1 = __floats2half2_rn(y2, y3);
        o.x = *(uint32_t*)&q0; o.y = *(uint32_t*)&q1;
        ((uint2*)g_qH)[(size_t)t * 64 + idx] = o;
    }
}

// ================= ln2: warp-per-token, batch slice =================
__global__ void ln2_kernel(const float* __restrict__ x,
                           const float* __restrict__ gamma,
                           const float* __restrict__ beta,
                           int tokOff) {
    const int wid = threadIdx.x >> 5, lane = threadIdx.x & 31;
    const int t = tokOff + blockIdx.x * 8 + wid;

    const float4* rowX = (const float4*)(x + (size_t)t * 256);
    float4 va = rowX[lane], vb = rowX[lane + 32];

    float s  = va.x + va.y + va.z + va.w + vb.x + vb.y + vb.z + vb.w;
    float s2 = va.x*va.x + va.y*va.y + va.z*va.z + va.w*va.w
             + vb.x*vb.x + vb.y*vb.y + vb.z*vb.z + vb.w*vb.w;
    #pragma unroll
    for (int o = 16; o; o >>= 1) {
        s  += __shfl_xor_sync(0xffffffffu, s,  o);
        s2 += __shfl_xor_sync(0xffffffffu, s2, o);
    }
    float mu  = s * (1.0f / D_MODEL);
    float var = s2 * (1.0f / D_MODEL) - mu * mu;
    float rr  = rsqrtf(var + 1e-5f);

    const float4* gmA = (const float4*)gamma;
    const float4* btA = (const float4*)beta;
    #pragma unroll
    for (int hfl = 0; hfl < 2; hfl++) {
        int idx = lane + hfl * 32;
        float4 v = hfl ? vb : va;
        float4 gm = gmA[idx], bt = btA[idx];
        float y0 = (v.x - mu) * rr * gm.x + bt.x;
        float y1 = (v.y - mu) * rr * gm.y + bt.y;
        float y2 = (v.z - mu) * rr * gm.z + bt.z;
        float y3 = (v.w - mu) * rr * gm.w + bt.w;
        uint2 o;
        __half2 q0 = __floats2half2_rn(y0, y1), q1 = __floats2half2_rn(y2, y3);
        o.x = *(uint32_t*)&q0; o.y = *(uint32_t*)&q1;
        ((uint2*)g_h2H)[(size_t)t * 64 + idx] = o;
    }
}

// ================= deform v7: 2 head-jobs per warp, folded fp16 weights =================
// Warp handles (tok, h0) and (tok, h0+1). Precompute: lane = j*16+sidx owns point sidx
// of job j. Two 4-iter main loops (quarter-warp per point, LDG.64).
__global__ void deform_kernel(const float* __restrict__ ref, int bIdx) {
    const int lvH[4] = {128, 64, 32, 16};
    const int lvW[4] = {128, 64, 32, 16};
    const int lvS[4] = {0, 16384, 20480, 21504};

    int p = blockIdx.x * 8 + (threadIdx.x >> 5);    // 0 .. SLEN*4-1
    int lane = threadIdx.x & 31;
    int qi = p >> 2;
    int h0 = (p & 3) * 2;
    int tok = bIdx * SLEN + qi;

    // --- prefetch: 64 offsets (2 heads), 8 ref floats, 32 logits (2 heads) ---
    float offA = g_off[(size_t)tok * 256 + h0 * 32 + lane];
    float offB = g_off[(size_t)tok * 256 + h0 * 32 + 32 + lane];
    float refv = (lane < 8) ? ref[(size_t)tok * 8 + lane] : 0.f;
    float lg   = g_attn[(size_t)tok * 128 + h0 * 16 + lane];   // lanes 0-15: h0, 16-31: h0+1

    // softmax within each 16-lane group
    float mx = lg;
    #pragma unroll
    for (int o = 8; o; o >>= 1) mx = fmaxf(mx, __shfl_xor_sync(0xffffffffu, mx, o));
    float e = __expf(lg - mx);
    float se = e;
    #pragma unroll
    for (int o = 8; o; o >>= 1) se += __shfl_xor_sync(0xffffffffu, se, o);
    float wnorm = e / se;                    // this lane's own point weight

    // --- precompute: lane = j*16 + sidx owns point sidx of head h0+j ---
    uint32_t c00, c01, c10, c11;
    uint32_t uh00, uh01, uh10, uh11;
    {
        const int j    = lane >> 4;
        const int sidx = lane & 15;
        const int lvl  = sidx >> 2;
        const int Ww = lvW[lvl], Hh = lvH[lvl];
        float rx = __shfl_sync(0xffffffffu, refv, lvl * 2 + 0);
        float ry = __shfl_sync(0xffffffffu, refv, lvl * 2 + 1);
        float oxA = __shfl_sync(0xffffffffu, offA, sidx * 2 + 0);
        float oyA = __shfl_sync(0xffffffffu, offA, sidx * 2 + 1);
        float oxB = __shfl_sync(0xffffffffu, offB, sidx * 2 + 0);
        float oyB = __shfl_sync(0xffffffffu, offB, sidx * 2 + 1);
        float ox = j ? oxB : oxA;
        float oy = j ? oyB : oyA;
        float wat = wnorm;                  // lane index == (h0+j)*16+sidx logit

        float x = fmaf(rx, (float)Ww, ox) - 0.5f;
        float y = fmaf(ry, (float)Hh, oy) - 0.5f;
        float x0f = floorf(x), y0f = floorf(y);
        int x0 = (int)x0f, y0 = (int)y0f;
        float wx = x - x0f, wy = y - y0f;
        int x1 = x0 + 1, y1 = y0 + 1;

        float vx0 = ((unsigned)x0 < (unsigned)Ww) ? 1.f : 0.f;
        float vx1 = ((unsigned)x1 < (unsigned)Ww) ? 1.f : 0.f;
        float vy0 = ((unsigned)y0 < (unsigned)Hh) ? 1.f : 0.f;
        float vy1 = ((unsigned)y1 < (unsigned)Hh) ? 1.f : 0.f;

        int x0c = min(max(x0, 0), Ww - 1), x1c = min(max(x1, 0), Ww - 1);
        int y0c = min(max(y0, 0), Hh - 1), y1c = min(max(y1, 0), Hh - 1);

        uint32_t pb = (uint32_t)(h0 + j) * NTOK + (uint32_t)(bIdx * SLEN + lvS[lvl]);
        uint32_t r0 = pb + (uint32_t)(y0c * Ww), r1 = pb + (uint32_t)(y1c * Ww);
        c00 = (r0 + (uint32_t)x0c) * 8u; c01 = (r0 + (uint32_t)x1c) * 8u;
        c10 = (r1 + (uint32_t)x0c) * 8u; c11 = (r1 + (uint32_t)x1c) * 8u;

        float wx0 = 1.f - wx, wy0 = 1.f - wy;
        __half2 t0 = __float2half2_rn(wat * wx0 * wy0 * (vx0 * vy0));
        __half2 t1 = __float2half2_rn(wat * wx  * wy0 * (vx1 * vy0));
        __half2 t2 = __float2half2_rn(wat * wx0 * wy  * (vx0 * vy1));
        __half2 t3 = __float2half2_rn(wat * wx  * wy  * (vx1 * vy1));
        uh00 = *(uint32_t*)&t0; uh01 = *(uint32_t*)&t1;
        uh10 = *(uint32_t*)&t2; uh11 = *(uint32_t*)&t3;
    }

    const int q = lane >> 3;
    const uint32_t li = (uint32_t)(lane & 7);
    const uint2* vbase = (const uint2*)g_valueH;

    float4 accA = make_float4(0.f, 0.f, 0.f, 0.f);
    float4 accB = make_float4(0.f, 0.f, 0.f, 0.f);
    #pragma unroll
    for (int jj = 0; jj < 2; jj++) {
        float4& acc = jj ? accB : accA;
        #pragma unroll
        for (int it = 0; it < 4; it++) {
            const int sl = jj * 16 + it * 4 + q;        // source lane owning this point
            uint32_t a00 = __shfl_sync(0xffffffffu, c00, sl) + li;
            uint32_t a01 = __shfl_sync(0xffffffffu, c01, sl) + li;
            uint32_t a10 = __shfl_sync(0xffffffffu, c10, sl) + li;
            uint32_t a11 = __shfl_sync(0xffffffffu, c11, sl) + li;
            uint32_t b00 = __shfl_sync(0xffffffffu, uh00, sl);
            uint32_t b01 = __shfl_sync(0xffffffffu, uh01, sl);
            uint32_t b10 = __shfl_sync(0xffffffffu, uh10, sl);
            uint32_t b11 = __shfl_sync(0xffffffffu, uh11, sl);
            uint2 r00 = vbase[a00];
            uint2 r01 = vbase[a01];
            uint2 r10 = vbase[a10];
            uint2 r11 = vbase[a11];
            __half2 blo = __hmul2(*(__half2*)&b00, *(__half2*)&r00.x);
            blo = __hfma2(*(__half2*)&b01, *(__half2*)&r01.x, blo);
            blo = __hfma2(*(__half2*)&b10, *(__half2*)&r10.x, blo);
            blo = __hfma2(*(__half2*)&b11, *(__half2*)&r11.x, blo);
            __half2 bhi = __hmul2(*(__half2*)&b00, *(__half2*)&r00.y);
            bhi = __hfma2(*(__half2*)&b01, *(__half2*)&r01.y, bhi);
            bhi = __hfma2(*(__half2*)&b10, *(__half2*)&r10.y, bhi);
            bhi = __hfma2(*(__half2*)&b11, *(__half2*)&r11.y, bhi);
            float2 f0 = __half22float2(blo);
            float2 f1 = __half22float2(bhi);
            acc.x += f0.x; acc.y += f0.y; acc.z += f1.x; acc.w += f1.y;
        }
    }
    // reduce across the 4 quarters for each job
    #pragma unroll
    for (int o = 8; o <= 16; o <<= 1) {
        accA.x += __shfl_xor_sync(0xffffffffu, accA.x, o);
        accA.y += __shfl_xor_sync(0xffffffffu, accA.y, o);
        accA.z += __shfl_xor_sync(0xffffffffu, accA.z, o);
        accA.w += __shfl_xor_sync(0xffffffffu, accA.w, o);
        accB.x += __shfl_xor_sync(0xffffffffu, accB.x, o);
        accB.y += __shfl_xor_sync(0xffffffffu, accB.y, o);
        accB.z += __shfl_xor_sync(0xffffffffu, accB.z, o);
        accB.w += __shfl_xor_sync(0xffffffffu, accB.w, o);
    }
    if (lane < 8) {
        uint2 o0, o1;
        __half2 ha0 = __floats2half2_rn(accA.x, accA.y), ha1 = __floats2half2_rn(accA.z, accA.w);
        __half2 hb0 = __floats2half2_rn(accB.x, accB.y), hb1 = __floats2half2_rn(accB.z, accB.w);
        o0.x = *(const uint32_t*)&ha0; o0.y = *(const uint32_t*)&ha1;
        o1.x = *(const uint32_t*)&hb0; o1.y = *(const uint32_t*)&hb1;
        ((uint2*)g_sampH)[(uint32_t)tok * 64u + (uint32_t)h0 * 8u + li] = o0;
        ((uint2*)g_sampH)[(uint32_t)tok * 64u + (uint32_t)(h0 + 1) * 8u + li] = o1;
    }
}

// ================= launch: batch-split symmetric dual-stream (R14 schedule) =================
extern "C" void kernel_launch(void* const* d_in, const int* in_sizes, int n_in,
                              void* d_out, int out_size) {
    const float* src  = (const float*)d_in[0];
    const float* pos  = (const float*)d_in[1];
    const float* refp = (const float*)d_in[2];
    const float* n1g = (const float*)d_in[5];
    const float* n1b = (const float*)d_in[6];
    const float* n2g = (const float*)d_in[7];
    const float* n2b = (const float*)d_in[8];
    const float* Wv  = (const float*)d_in[9];
    const float* bv  = (const float*)d_in[10];
    const float* Wo  = (const float*)d_in[11];
    const float* bo  = (const float*)d_in[12];
    const float* Wa  = (const float*)d_in[13];
    const float* ba  = (const float*)d_in[14];
    const float* Wout= (const float*)d_in[15];
    const float* bout= (const float*)d_in[16];
    const float* Wf1 = (const float*)d_in[17];
    const float* bf1 = (const float*)d_in[18];
    const float* Wf2 = (const float*)d_in[19];
    const float* bf2 = (const float*)d_in[20];
    float* out = (float*)d_out;

    __half *srcH, *qH, *sampH, *h2H, *ffnH, *valH;
    __half *wv, *wqa, *wo, *wf1, *wf2;
    float *pOff, *pAttn, *pSrc2;
    cudaGetSymbolAddress((void**)&srcH, g_srcH);
    cudaGetSymbolAddress((void**)&qH,   g_qH);
    cudaGetSymbolAddress((void**)&sampH,g_sampH);
    cudaGetSymbolAddress((void**)&h2H,  g_h2H);
    cudaGetSymbolAddress((void**)&ffnH, g_ffnH);
    cudaGetSymbolAddress((void**)&valH, g_valueH);
    cudaGetSymbolAddress((void**)&wv,   w_v);
    cudaGetSymbolAddress((void**)&wqa,  w_qa);
    cudaGetSymbolAddress((void**)&wo,   w_o);
    cudaGetSymbolAddress((void**)&wf1,  w_f1);
    cudaGetSymbolAddress((void**)&wf2,  w_f2);
    cudaGetSymbolAddress((void**)&pOff,  g_off);
    cudaGetSymbolAddress((void**)&pAttn, g_attn);
    cudaGetSymbolAddress((void**)&pSrc2, g_src2);

    cudaFuncSetAttribute(mma_gemm<1>, cudaFuncAttributeMaxDynamicSharedMemorySize, GEMM_SMEM);
    cudaFuncSetAttribute(mma_gemm<2>, cudaFuncAttributeMaxDynamicSharedMemorySize, GEMM_SMEM);
    cudaFuncSetAttribute(mma_gemm<3>, cudaFuncAttributeMaxDynamicSharedMemorySize, GEMM_SMEM);
    cudaFuncSetAttribute(mma_gemm<4>, cudaFuncAttributeMaxDynamicSharedMemorySize, GEMM_SMEM);

    static cudaStream_t sB = nullptr;
    static cudaEvent_t evPre = nullptr, evB = nullptr;
    if (!sB) {
        cudaStreamCreateWithFlags(&sB, cudaStreamNonBlocking);
        cudaEventCreateWithFlags(&evPre, cudaEventDisableTiming);
        cudaEventCreateWithFlags(&evB,   cudaEventDisableTiming);
    }

    dim3 t256(256), t128(128);
    const int MBb = SLEN / 128;   // 170 row-tiles per batch

    pre_kernel<<<NTOK / 8, t256>>>(src, n1g, n1b, pos, Wv, Wo, Wa, Wout, Wf1, Wf2);
    cudaEventRecord(evPre, 0);
    cudaStreamWaitEvent(sB, evPre, 0);

    for (int b = 0; b < 2; b++) {
        cudaStream_t st = (b == 0) ? (cudaStream_t)0 : sB;
        const size_t to = (size_t)b * SLEN;
        const __half* srcHb = srcH + to * 256;
        const __half* qHb   = qH   + to * 256;
        __half*  valHb  = valH + to * 32;
        float*   offb   = pOff  + to * 256;
        float*   attnb  = pAttn + to * 128;
        __half*  sampb  = sampH + to * 256;
        float*   src2b  = pSrc2 + to * 256;
        const float* srcb = src + to * 256;
        __half*  h2b    = h2H  + to * 256;
        __half*  ffnb   = ffnH + to * 1024;
        float*   outb   = out  + to * 256;

        mma_gemm<4><<<dim3(2, MBb), t128, GEMM_SMEM, st>>>(srcHb, wv, bv, nullptr,
                                                           nullptr, nullptr, valHb, 256, 256);
        mma_gemm<3><<<dim3(3, MBb), t128, GEMM_SMEM, st>>>(qHb, wqa, bo, ba,
                                                           offb, attnb, nullptr, 384, 256);
        deform_kernel<<<(SLEN * 4) / 8, t256, 0, st>>>(refp, b);
        mma_gemm<2><<<dim3(2, MBb), t128, GEMM_SMEM, st>>>(sampb, wo, bout, srcb,
                                                           src2b, nullptr, nullptr, 256, 256);
        ln2_kernel<<<SLEN / 8, t256, 0, st>>>(pSrc2, n2g, n2b, (int)to);
        mma_gemm<1><<<dim3(8, MBb), t128, GEMM_SMEM, st>>>(h2b, wf1, bf1, nullptr,
                                                           nullptr, nullptr, ffnb, 1024, 256);
        mma_gemm<2><<<dim3(2, MBb), t128, GEMM_SMEM, st>>>(ffnb, wf2, bf2, src2b,
                                                           outb, nullptr, nullptr, 256, 1024);
    }

    cudaEventRecord(evB, sB);
    cudaStreamWaitEvent(0, evB, 0);
}